// round 1
// baseline (speedup 1.0000x reference)
#include <cuda_runtime.h>
#include <cstdint>

#define N_NODES 100000
#define N_EDGES 1600000
#define TM 64
#define THREADS 256

// Scratch (no allocations allowed): per-node [sum_ea0, sum_ea1, sum_ea2, count]
__device__ float4 g_agg[N_NODES];
// Wsum = W1[0:128,:] + W1[128:256,:]
__device__ float4 g_wsum[128 * 32];
__device__ int g_idx64;

// ---------------------------------------------------------------------------
// prep: zero agg, build Wsum, detect edge_index dtype (int64 vs int32)
// ---------------------------------------------------------------------------
__global__ void prep_kernel(const int* __restrict__ ei32, const float* __restrict__ W1) {
    int tid = blockIdx.x * blockDim.x + threadIdx.x;
    int stride = gridDim.x * blockDim.x;
    float* aggf = (float*)g_agg;
    for (int i = tid; i < N_NODES * 4; i += stride) aggf[i] = 0.0f;
    float* ws = (float*)g_wsum;
    for (int i = tid; i < 128 * 128; i += stride)
        ws[i] = W1[i] + W1[128 * 128 + i];
    if (tid == 0) {
        // int64 little-endian: odd 32-bit words are high words == 0 (ids < 2^31).
        // int32: those are random node ids; all-zero prob ~1e-20.
        g_idx64 = ((ei32[1] | ei32[3] | ei32[5] | ei32[7]) == 0) ? 1 : 0;
    }
}

// ---------------------------------------------------------------------------
// scatter: segment-sum of edge_attr (3 floats) + count, keyed by src
// ---------------------------------------------------------------------------
__global__ void scatter_kernel(const int* __restrict__ ei32, const float* __restrict__ ea) {
    int e = blockIdx.x * blockDim.x + threadIdx.x;
    if (e >= N_EDGES) return;
    int src;
    if (g_idx64) src = ei32[2 * (N_EDGES + e)];   // low word of edge_index[1][e]
    else         src = ei32[N_EDGES + e];
    float a0 = ea[e * 3 + 0];
    float a1 = ea[e * 3 + 1];
    float a2 = ea[e * 3 + 2];
    atomicAdd(&g_agg[src].x, a0);
    atomicAdd(&g_agg[src].y, a1);
    atomicAdd(&g_agg[src].z, a2);
    atomicAdd(&g_agg[src].w, 1.0f);
}

// ---------------------------------------------------------------------------
// fused: h1 = relu(x@Wsel + mea@W1c + b1); out = h1@W2 + b2
// 64 nodes x 128 cols per block; 256 threads; each thread 8x4 micro-tile.
// ---------------------------------------------------------------------------
__global__ __launch_bounds__(THREADS, 1)
void fused_kernel(const float* __restrict__ x,
                  const float* __restrict__ W1,
                  const float* __restrict__ b1,
                  const float* __restrict__ W2,
                  const float* __restrict__ b2,
                  float* __restrict__ out) {
    extern __shared__ float smem[];
    float* sA  = smem;                 // [TM][128]  x tile, then reused read-only
    float* sW  = sA + TM * 128;        // [128][128] current weight matrix
    float* sH  = sW + 128 * 128;       // [TM][128]  hidden
    float* sC  = sH + TM * 128;        // [3][128]   W1c rows
    float* sB1 = sC + 3 * 128;
    float* sB2 = sB1 + 128;
    float* sM  = sB2 + 128;            // [TM][4] mea0,mea1,mea2,f

    const int tid = threadIdx.x;
    const int node0 = blockIdx.x * TM;
    float4* sA4 = (float4*)sA;
    float4* sW4 = (float4*)sW;
    float4* sH4 = (float4*)sH;

    // ---- load X tile (zero-fill past N) ----
    const float4* x4 = (const float4*)x;
    for (int i = tid; i < TM * 32; i += THREADS) {
        int n = i >> 5;
        int g = node0 + n;
        float4 v = make_float4(0.f, 0.f, 0.f, 0.f);
        if (g < N_NODES) v = x4[g * 32 + (i & 31)];
        sA4[i] = v;
    }
    if (tid < 128) { sB1[tid] = b1[tid]; sB2[tid] = b2[tid]; }
    for (int i = tid; i < 3 * 128; i += THREADS) sC[i] = W1[256 * 128 + i];

    // ---- per-node mean edge_attr + flag ----
    int myf = 1;
    if (tid < TM) {
        int g = node0 + tid;
        float4 a = make_float4(0.f, 0.f, 0.f, 0.f);
        if (g < N_NODES) a = g_agg[g];
        float f = (a.w > 0.f) ? 1.0f : 0.0f;
        float inv = 1.0f / fmaxf(a.w, 1.0f);
        sM[tid * 4 + 0] = a.x * inv;
        sM[tid * 4 + 1] = a.y * inv;
        sM[tid * 4 + 2] = a.z * inv;
        sM[tid * 4 + 3] = f;
        myf = (g < N_NODES) ? (int)f : 1;   // padding nodes don't force slow path
    }
    int allf = __syncthreads_and(myf);

    const int nr = tid >> 5;   // node group: nodes nr*8 .. nr*8+7
    const int cg = tid & 31;   // col group:  cols  cg*4 .. cg*4+3

    float acc[8][4];
#pragma unroll
    for (int i = 0; i < 8; i++)
#pragma unroll
        for (int c = 0; c < 4; c++) acc[i][c] = 0.f;

#define GEMM_PASS(SCALED)                                                      \
    _Pragma("unroll 2")                                                        \
    for (int k4 = 0; k4 < 32; k4++) {                                          \
        float4 w0 = sW4[(k4 * 4 + 0) * 32 + cg];                               \
        float4 w1 = sW4[(k4 * 4 + 1) * 32 + cg];                               \
        float4 w2 = sW4[(k4 * 4 + 2) * 32 + cg];                               \
        float4 w3 = sW4[(k4 * 4 + 3) * 32 + cg];                               \
        _Pragma("unroll")                                                      \
        for (int i = 0; i < 8; i++) {                                          \
            float4 a = sA4[(nr * 8 + i) * 32 + k4];                            \
            if (SCALED) {                                                      \
                float fi = sM[(nr * 8 + i) * 4 + 3];                           \
                a.x *= fi; a.y *= fi; a.z *= fi; a.w *= fi;                    \
            }                                                                  \
            acc[i][0] += a.x * w0.x; acc[i][1] += a.x * w0.y;                  \
            acc[i][2] += a.x * w0.z; acc[i][3] += a.x * w0.w;                  \
            acc[i][0] += a.y * w1.x; acc[i][1] += a.y * w1.y;                  \
            acc[i][2] += a.y * w1.z; acc[i][3] += a.y * w1.w;                  \
            acc[i][0] += a.z * w2.x; acc[i][1] += a.z * w2.y;                  \
            acc[i][2] += a.z * w2.z; acc[i][3] += a.z * w2.w;                  \
            acc[i][0] += a.w * w3.x; acc[i][1] += a.w * w3.y;                  \
            acc[i][2] += a.w * w3.z; acc[i][3] += a.w * w3.w;                  \
        }                                                                      \
    }

    if (allf) {
        // fast path: single K=128 pass with Wsum (f==1 for all nodes in tile)
        for (int i = tid; i < 128 * 32; i += THREADS) sW4[i] = g_wsum[i];
        __syncthreads();
        GEMM_PASS(0)
    } else {
        // slow path: acc = x@W1a + f * (x@W1b)
        const float4* w4g = (const float4*)W1;
        for (int i = tid; i < 128 * 32; i += THREADS) sW4[i] = w4g[i];
        __syncthreads();
        GEMM_PASS(0)
        __syncthreads();
        for (int i = tid; i < 128 * 32; i += THREADS) sW4[i] = w4g[128 * 32 + i];
        __syncthreads();
        GEMM_PASS(1)
    }

    // ---- epilogue A: + b1 + mea@W1c, relu -> sH ----
#pragma unroll
    for (int i = 0; i < 8; i++) {
        int n = nr * 8 + i;
        float m0 = sM[n * 4 + 0], m1 = sM[n * 4 + 1], m2 = sM[n * 4 + 2];
#pragma unroll
        for (int c = 0; c < 4; c++) {
            int j = cg * 4 + c;
            float v = acc[i][c] + sB1[j] + m0 * sC[j] + m1 * sC[128 + j] + m2 * sC[256 + j];
            sH[n * 128 + j] = fmaxf(v, 0.0f);
        }
    }
    __syncthreads();

    // ---- load W2, phase B ----
    {
        const float4* w4g = (const float4*)W2;
        for (int i = tid; i < 128 * 32; i += THREADS) sW4[i] = w4g[i];
    }
#pragma unroll
    for (int i = 0; i < 8; i++)
#pragma unroll
        for (int c = 0; c < 4; c++) acc[i][c] = 0.f;
    __syncthreads();

#pragma unroll 2
    for (int k4 = 0; k4 < 32; k4++) {
        float4 w0 = sW4[(k4 * 4 + 0) * 32 + cg];
        float4 w1 = sW4[(k4 * 4 + 1) * 32 + cg];
        float4 w2 = sW4[(k4 * 4 + 2) * 32 + cg];
        float4 w3 = sW4[(k4 * 4 + 3) * 32 + cg];
#pragma unroll
        for (int i = 0; i < 8; i++) {
            float4 a = sH4[(nr * 8 + i) * 32 + k4];
            acc[i][0] += a.x * w0.x; acc[i][1] += a.x * w0.y;
            acc[i][2] += a.x * w0.z; acc[i][3] += a.x * w0.w;
            acc[i][0] += a.y * w1.x; acc[i][1] += a.y * w1.y;
            acc[i][2] += a.y * w1.z; acc[i][3] += a.y * w1.w;
            acc[i][0] += a.z * w2.x; acc[i][1] += a.z * w2.y;
            acc[i][2] += a.z * w2.z; acc[i][3] += a.z * w2.w;
            acc[i][0] += a.w * w3.x; acc[i][1] += a.w * w3.y;
            acc[i][2] += a.w * w3.z; acc[i][3] += a.w * w3.w;
        }
    }

    // ---- epilogue B: + b2, store ----
    float4* out4 = (float4*)out;
#pragma unroll
    for (int i = 0; i < 8; i++) {
        int g = node0 + nr * 8 + i;
        if (g < N_NODES) {
            int j = cg * 4;
            float4 v;
            v.x = acc[i][0] + sB2[j + 0];
            v.y = acc[i][1] + sB2[j + 1];
            v.z = acc[i][2] + sB2[j + 2];
            v.w = acc[i][3] + sB2[j + 3];
            out4[g * 32 + cg] = v;
        }
    }
#undef GEMM_PASS
}

// ---------------------------------------------------------------------------
extern "C" void kernel_launch(void* const* d_in, const int* in_sizes, int n_in,
                              void* d_out, int out_size) {
    const float* x    = (const float*)d_in[0];
    const int*   ei32 = (const int*)d_in[1];   // int64 or int32, detected at runtime
    const float* ea   = (const float*)d_in[2];
    // d_in[3] = u (unused), d_in[4] = batch (unused)
    const float* W1   = (const float*)d_in[5];
    const float* b1   = (const float*)d_in[6];
    const float* W2   = (const float*)d_in[7];
    const float* b2   = (const float*)d_in[8];
    float* out = (float*)d_out;

    size_t smem_bytes = (size_t)(TM * 128 + 128 * 128 + TM * 128 + 3 * 128 + 128 + 128 + TM * 4) * sizeof(float);
    cudaFuncSetAttribute(fused_kernel, cudaFuncAttributeMaxDynamicSharedMemorySize, (int)smem_bytes);

    prep_kernel<<<64, 256>>>(ei32, W1);
    scatter_kernel<<<(N_EDGES + 255) / 256, 256>>>(ei32, ea);
    fused_kernel<<<(N_NODES + TM - 1) / TM, THREADS, smem_bytes>>>(x, W1, b1, W2, b2, out);
}

// round 5
// speedup vs baseline: 1.6969x; 1.6969x over previous
#include <cuda_runtime.h>
#include <cuda_bf16.h>
#include <cstdint>

#define N_NODES 100000
#define N_EDGES 1600000
#define TM 128
#define NBLK ((N_NODES + TM - 1) / TM)
#define THREADS 256
#define LDK 136   // padded K stride (odd 16B stride -> conflict-free frag loads)

// ---- SMEM byte offsets ----
#define OFF_AHI 0                    // 34816  [128][136] bf16
#define OFF_ALO 34816
#define OFF_BHI 69632
#define OFF_BLO 104448
#define OFF_MEA 139264               // [128][4] fp32
#define OFF_W1C 141312               // [3][128] fp32
#define OFF_B1  142848               // [128] fp32
#define OFF_B2  143360               // [128] fp32
#define SMEM_TOTAL 143872

// ---- global scratch ----
__device__ float4 g_agg[N_NODES];                      // sum_ea0..2, count
__device__ __align__(16) __nv_bfloat16 g_B1hi[128 * LDK];  // [n][k] = Wsum[k][n]
__device__ __align__(16) __nv_bfloat16 g_B1lo[128 * LDK];
__device__ __align__(16) __nv_bfloat16 g_B2hi[128 * LDK];  // [n][k] = W2[k][n]
__device__ __align__(16) __nv_bfloat16 g_B2lo[128 * LDK];
__device__ int g_idx64;
__device__ int g_nzero;
__device__ int g_zlist[4096];

__device__ __forceinline__ uint32_t pack_bf(float a, float b) {
    __nv_bfloat162 t = __floats2bfloat162_rn(a, b);
    return *(uint32_t*)&t;
}
__device__ __forceinline__ float bf_resid(float v) {
    return v - __bfloat162float(__float2bfloat16_rn(v));
}
__device__ __forceinline__ void mma_bf16(float* c, const uint32_t* a, const uint32_t* b) {
    asm volatile(
        "mma.sync.aligned.m16n8k16.row.col.f32.bf16.bf16.f32 "
        "{%0,%1,%2,%3}, {%4,%5,%6,%7}, {%8,%9}, {%0,%1,%2,%3};"
        : "+f"(c[0]), "+f"(c[1]), "+f"(c[2]), "+f"(c[3])
        : "r"(a[0]), "r"(a[1]), "r"(a[2]), "r"(a[3]), "r"(b[0]), "r"(b[1]));
}

// ---------------------------------------------------------------------------
// prep: zero agg, build bf16 hi/lo transposed weight images, detect idx dtype
// ---------------------------------------------------------------------------
__global__ void prep_kernel(const int* __restrict__ ei32,
                            const float* __restrict__ W1,
                            const float* __restrict__ W2) {
    int tid = blockIdx.x * blockDim.x + threadIdx.x;
    int stride = gridDim.x * blockDim.x;
    float* aggf = (float*)g_agg;
    for (int i = tid; i < N_NODES * 4; i += stride) aggf[i] = 0.0f;
    for (int i = tid; i < 128 * 128; i += stride) {
        int n = i >> 7, k = i & 127;
        float v = W1[k * 128 + n] + W1[(128 + k) * 128 + n];   // Wsum^T
        __nv_bfloat16 h = __float2bfloat16_rn(v);
        g_B1hi[n * LDK + k] = h;
        g_B1lo[n * LDK + k] = __float2bfloat16_rn(v - __bfloat162float(h));
        float w = W2[k * 128 + n];                              // W2^T
        __nv_bfloat16 h2 = __float2bfloat16_rn(w);
        g_B2hi[n * LDK + k] = h2;
        g_B2lo[n * LDK + k] = __float2bfloat16_rn(w - __bfloat162float(h2));
    }
    // zero the pad columns so no uninitialized bytes flow anywhere
    for (int i = tid; i < 128 * (LDK - 128); i += stride) {
        int n = i / (LDK - 128), k = 128 + i % (LDK - 128);
        g_B1hi[n * LDK + k] = __float2bfloat16_rn(0.f);
        g_B1lo[n * LDK + k] = __float2bfloat16_rn(0.f);
        g_B2hi[n * LDK + k] = __float2bfloat16_rn(0.f);
        g_B2lo[n * LDK + k] = __float2bfloat16_rn(0.f);
    }
    if (tid == 0) {
        g_nzero = 0;
        g_idx64 = ((ei32[1] | ei32[3] | ei32[5] | ei32[7]) == 0) ? 1 : 0;
    }
}

// ---------------------------------------------------------------------------
// scatter: segment-sum of edge_attr (3 floats) + count, keyed by src
// ---------------------------------------------------------------------------
__global__ void scatter_kernel(const int* __restrict__ ei32, const float* __restrict__ ea) {
    int e = blockIdx.x * blockDim.x + threadIdx.x;
    if (e >= N_EDGES) return;
    int src;
    if (g_idx64) src = ei32[2 * (N_EDGES + e)];
    else         src = ei32[N_EDGES + e];
    float a0 = ea[e * 3 + 0];
    float a1 = ea[e * 3 + 1];
    float a2 = ea[e * 3 + 2];
    atomicAdd(&g_agg[src].x, a0);
    atomicAdd(&g_agg[src].y, a1);
    atomicAdd(&g_agg[src].z, a2);
    atomicAdd(&g_agg[src].w, 1.0f);
}

// ---------------------------------------------------------------------------
// fused: 2 layers of split-bf16 mma.sync GEMM per 128-node tile
// ---------------------------------------------------------------------------
__global__ __launch_bounds__(THREADS, 1)
void fused_kernel(const float* __restrict__ x,
                  const float* __restrict__ W1,
                  const float* __restrict__ b1g,
                  const float* __restrict__ b2g,
                  float* __restrict__ out) {
    extern __shared__ char smem[];
    __nv_bfloat16* sAhi = (__nv_bfloat16*)(smem + OFF_AHI);
    __nv_bfloat16* sAlo = (__nv_bfloat16*)(smem + OFF_ALO);
    __nv_bfloat16* sBhi = (__nv_bfloat16*)(smem + OFF_BHI);
    __nv_bfloat16* sBlo = (__nv_bfloat16*)(smem + OFF_BLO);
    float* sMea = (float*)(smem + OFF_MEA);
    float* sW1c = (float*)(smem + OFF_W1C);
    float* sB1  = (float*)(smem + OFF_B1);
    float* sB2  = (float*)(smem + OFF_B2);

    const int tid = threadIdx.x, wid = tid >> 5, lane = tid & 31;
    const int gID = lane >> 2, tIG = lane & 3;
    const int node0 = blockIdx.x * TM;
    const int wr = (wid & 1) * 64;      // warp row base
    const int wc = (wid >> 1) * 32;     // warp col base

    // ---- stage biases, W1c ----
    if (tid < 128) { sB1[tid] = b1g[tid]; sB2[tid] = b2g[tid]; }
    for (int i = tid; i < 3 * 128; i += THREADS) sW1c[i] = W1[256 * 128 + i];

    // ---- mea + zero-degree detect ----
    if (tid < TM) {
        int g = node0 + tid;
        float4 a = make_float4(0.f, 0.f, 0.f, 1.f);
        if (g < N_NODES) {
            a = g_agg[g];
            if (a.w == 0.f) {
                int p = atomicAdd(&g_nzero, 1);
                if (p >= 0 && p < 4096) g_zlist[p] = g;
            }
        }
        float inv = 1.0f / fmaxf(a.w, 1.0f);
        sMea[tid * 4 + 0] = a.x * inv;
        sMea[tid * 4 + 1] = a.y * inv;
        sMea[tid * 4 + 2] = a.z * inv;
    }

    // ---- x -> sA hi/lo ----
    const float4* x4 = (const float4*)x;
    for (int idx = tid; idx < TM * 32; idx += THREADS) {
        int r = idx >> 5, kq = idx & 31, g = node0 + r;
        float4 v = make_float4(0.f, 0.f, 0.f, 0.f);
        if (g < N_NODES) v = x4[g * 32 + kq];
        int o = r * LDK + kq * 4;
        *(uint32_t*)(sAhi + o)     = pack_bf(v.x, v.y);
        *(uint32_t*)(sAhi + o + 2) = pack_bf(v.z, v.w);
        *(uint32_t*)(sAlo + o)     = pack_bf(bf_resid(v.x), bf_resid(v.y));
        *(uint32_t*)(sAlo + o + 2) = pack_bf(bf_resid(v.z), bf_resid(v.w));
    }
    // ---- B1 copy (pre-built, L2-hot) ----
    {
        const uint4* s1 = (const uint4*)g_B1hi;
        const uint4* s2 = (const uint4*)g_B1lo;
        uint4* d1 = (uint4*)sBhi;
        uint4* d2 = (uint4*)sBlo;
        for (int i = tid; i < 128 * LDK * 2 / 16; i += THREADS) { d1[i] = s1[i]; d2[i] = s2[i]; }
    }
    __syncthreads();

    float acc[4][4][4];
#pragma unroll
    for (int ma = 0; ma < 4; ma++)
#pragma unroll
        for (int na = 0; na < 4; na++)
#pragma unroll
            for (int c = 0; c < 4; c++) acc[ma][na][c] = 0.f;

#define MMA_LAYER()                                                             \
    _Pragma("unroll")                                                           \
    for (int ks = 0; ks < 8; ks++) {                                            \
        const int k0 = ks * 16 + tIG * 2;                                       \
        uint32_t aH[4][4], aL[4][4], bH[4][2], bL[4][2];                        \
        _Pragma("unroll")                                                       \
        for (int ma = 0; ma < 4; ma++) {                                        \
            int r = wr + ma * 16 + gID;                                         \
            aH[ma][0] = *(const uint32_t*)(sAhi + r * LDK + k0);                \
            aH[ma][1] = *(const uint32_t*)(sAhi + (r + 8) * LDK + k0);          \
            aH[ma][2] = *(const uint32_t*)(sAhi + r * LDK + k0 + 8);            \
            aH[ma][3] = *(const uint32_t*)(sAhi + (r + 8) * LDK + k0 + 8);      \
            aL[ma][0] = *(const uint32_t*)(sAlo + r * LDK + k0);                \
            aL[ma][1] = *(const uint32_t*)(sAlo + (r + 8) * LDK + k0);          \
            aL[ma][2] = *(const uint32_t*)(sAlo + r * LDK + k0 + 8);            \
            aL[ma][3] = *(const uint32_t*)(sAlo + (r + 8) * LDK + k0 + 8);      \
        }                                                                       \
        _Pragma("unroll")                                                       \
        for (int na = 0; na < 4; na++) {                                        \
            int n = wc + na * 8 + gID;                                          \
            bH[na][0] = *(const uint32_t*)(sBhi + n * LDK + k0);                \
            bH[na][1] = *(const uint32_t*)(sBhi + n * LDK + k0 + 8);            \
            bL[na][0] = *(const uint32_t*)(sBlo + n * LDK + k0);                \
            bL[na][1] = *(const uint32_t*)(sBlo + n * LDK + k0 + 8);            \
        }                                                                       \
        _Pragma("unroll")                                                       \
        for (int ma = 0; ma < 4; ma++)                                          \
            _Pragma("unroll")                                                   \
            for (int na = 0; na < 4; na++) {                                    \
                mma_bf16(acc[ma][na], aH[ma], bH[na]);                          \
                mma_bf16(acc[ma][na], aL[ma], bH[na]);                          \
                mma_bf16(acc[ma][na], aH[ma], bL[na]);                          \
            }                                                                   \
    }

    MMA_LAYER()
    __syncthreads();

    // ---- epilogue1: h = relu(acc + b1 + mea@W1c) -> sA hi/lo; reset acc ----
#pragma unroll
    for (int ma = 0; ma < 4; ma++) {
        int r0 = wr + ma * 16 + gID;
        float m00 = sMea[r0 * 4], m01 = sMea[r0 * 4 + 1], m02 = sMea[r0 * 4 + 2];
        int r1 = r0 + 8;
        float m10 = sMea[r1 * 4], m11 = sMea[r1 * 4 + 1], m12 = sMea[r1 * 4 + 2];
#pragma unroll
        for (int na = 0; na < 4; na++) {
            int c0 = wc + na * 8 + tIG * 2;
            float e0 = sB1[c0]     + m00 * sW1c[c0]     + m01 * sW1c[128 + c0]     + m02 * sW1c[256 + c0];
            float e1 = sB1[c0 + 1] + m00 * sW1c[c0 + 1] + m01 * sW1c[128 + c0 + 1] + m02 * sW1c[256 + c0 + 1];
            float f0 = sB1[c0]     + m10 * sW1c[c0]     + m11 * sW1c[128 + c0]     + m12 * sW1c[256 + c0];
            float f1 = sB1[c0 + 1] + m10 * sW1c[c0 + 1] + m11 * sW1c[128 + c0 + 1] + m12 * sW1c[256 + c0 + 1];
            float v0 = fmaxf(acc[ma][na][0] + e0, 0.f);
            float v1 = fmaxf(acc[ma][na][1] + e1, 0.f);
            float v2 = fmaxf(acc[ma][na][2] + f0, 0.f);
            float v3 = fmaxf(acc[ma][na][3] + f1, 0.f);
            *(uint32_t*)(sAhi + r0 * LDK + c0) = pack_bf(v0, v1);
            *(uint32_t*)(sAlo + r0 * LDK + c0) = pack_bf(bf_resid(v0), bf_resid(v1));
            *(uint32_t*)(sAhi + r1 * LDK + c0) = pack_bf(v2, v3);
            *(uint32_t*)(sAlo + r1 * LDK + c0) = pack_bf(bf_resid(v2), bf_resid(v3));
#pragma unroll
            for (int c = 0; c < 4; c++) acc[ma][na][c] = 0.f;
        }
    }
    // ---- B2 copy ----
    {
        const uint4* s1 = (const uint4*)g_B2hi;
        const uint4* s2 = (const uint4*)g_B2lo;
        uint4* d1 = (uint4*)sBhi;
        uint4* d2 = (uint4*)sBlo;
        for (int i = tid; i < 128 * LDK * 2 / 16; i += THREADS) { d1[i] = s1[i]; d2[i] = s2[i]; }
    }
    __syncthreads();

    MMA_LAYER()

    // ---- epilogue2: out = acc + b2 (direct global stores, 8B each) ----
#pragma unroll
    for (int ma = 0; ma < 4; ma++) {
        int r0 = wr + ma * 16 + gID;
        int g0 = node0 + r0, g1 = g0 + 8;
#pragma unroll
        for (int na = 0; na < 4; na++) {
            int c0 = wc + na * 8 + tIG * 2;
            if (g0 < N_NODES) {
                float2 v = make_float2(acc[ma][na][0] + sB2[c0], acc[ma][na][1] + sB2[c0 + 1]);
                *(float2*)(out + (size_t)g0 * 128 + c0) = v;
            }
            if (g1 < N_NODES) {
                float2 v = make_float2(acc[ma][na][2] + sB2[c0], acc[ma][na][3] + sB2[c0 + 1]);
                *(float2*)(out + (size_t)g1 * 128 + c0) = v;
            }
        }
    }
#undef MMA_LAYER
}

// ---------------------------------------------------------------------------
// fixup: exact fp32 recompute for zero-degree nodes (expected count: 0)
// ---------------------------------------------------------------------------
__global__ void fixup_kernel(const float* __restrict__ x,
                             const float* __restrict__ W1,
                             const float* __restrict__ b1,
                             const float* __restrict__ W2,
                             const float* __restrict__ b2,
                             float* __restrict__ out) {
    __shared__ float sh[128];
    int nz = *(volatile int*)&g_nzero;
    if (nz > 4096) nz = 4096;
    if (nz <= 0) return;
    int j = threadIdx.x;
    for (int zi = 0; zi < nz; zi++) {
        int n = g_zlist[zi];
        float acc = b1[j];
        for (int k = 0; k < 128; k++) acc = fmaf(x[n * 128 + k], W1[k * 128 + j], acc);
        sh[j] = fmaxf(acc, 0.f);
        __syncthreads();
        float acc2 = b2[j];
        for (int k = 0; k < 128; k++) acc2 = fmaf(sh[k], W2[k * 128 + j], acc2);
        out[n * 128 + j] = acc2;
        __syncthreads();
    }
}

// ---------------------------------------------------------------------------
extern "C" void kernel_launch(void* const* d_in, const int* in_sizes, int n_in,
                              void* d_out, int out_size) {
    const float* x    = (const float*)d_in[0];
    const int*   ei32 = (const int*)d_in[1];
    const float* ea   = (const float*)d_in[2];
    const float* W1   = (const float*)d_in[5];
    const float* b1   = (const float*)d_in[6];
    const float* W2   = (const float*)d_in[7];
    const float* b2   = (const float*)d_in[8];
    float* out = (float*)d_out;

    cudaFuncSetAttribute(fused_kernel, cudaFuncAttributeMaxDynamicSharedMemorySize, SMEM_TOTAL);

    prep_kernel<<<128, 256>>>(ei32, W1, W2);
    scatter_kernel<<<(N_EDGES + 255) / 256, 256>>>(ei32, ea);
    fused_kernel<<<NBLK, THREADS, SMEM_TOTAL>>>(x, W1, b1, b2, out);
    fixup_kernel<<<1, 128>>>(x, W1, b1, W2, b2, out);
}

// round 7
// speedup vs baseline: 2.8541x; 1.6819x over previous
#include <cuda_runtime.h>
#include <cuda_bf16.h>
#include <cstdint>

#define N_NODES 100000
#define N_EDGES 1600000
#define TM 128
#define NBLK ((N_NODES + TM - 1) / TM)
#define THREADS 256
#define NPERS 148     // persistent CTAs (~1 per SM)
#define LDK 136       // padded K stride (odd 16B stride -> conflict-free frag loads)

// ---- SMEM byte offsets (persistent layout: A + B1 + B2 resident together) ----
#define OFF_B1HI 0            // 34816 each  [128][136] bf16
#define OFF_B1LO 34816
#define OFF_B2HI 69632
#define OFF_B2LO 104448
#define OFF_AHI  139264
#define OFF_ALO  174080
#define OFF_MEA  208896       // [128][4] fp32
#define OFF_W1C  210944       // [3][128] fp32
#define OFF_B1   212480       // [128] fp32
#define OFF_B2   212992       // [128] fp32
#define SMEM_TOTAL 213504

// ---- global scratch ----
__device__ float4 g_agg[N_NODES];                      // sum_ea0..2, count
__device__ __align__(16) __nv_bfloat16 g_B1hi[128 * LDK];  // [n][k] = Wsum[k][n]
__device__ __align__(16) __nv_bfloat16 g_B1lo[128 * LDK];
__device__ __align__(16) __nv_bfloat16 g_B2hi[128 * LDK];  // [n][k] = W2[k][n]
__device__ __align__(16) __nv_bfloat16 g_B2lo[128 * LDK];
__device__ int g_idx64;
__device__ int g_nzero;
__device__ int g_zlist[4096];

__device__ __forceinline__ uint32_t pack_bf(float a, float b) {
    __nv_bfloat162 t = __floats2bfloat162_rn(a, b);
    return *(uint32_t*)&t;
}
__device__ __forceinline__ float bf_resid(float v) {
    return v - __bfloat162float(__float2bfloat16_rn(v));
}
__device__ __forceinline__ void mma_bf16(float* c, const uint32_t* a, const uint32_t* b) {
    asm volatile(
        "mma.sync.aligned.m16n8k16.row.col.f32.bf16.bf16.f32 "
        "{%0,%1,%2,%3}, {%4,%5,%6,%7}, {%8,%9}, {%0,%1,%2,%3};"
        : "+f"(c[0]), "+f"(c[1]), "+f"(c[2]), "+f"(c[3])
        : "r"(a[0]), "r"(a[1]), "r"(a[2]), "r"(a[3]), "r"(b[0]), "r"(b[1]));
}

// ---------------------------------------------------------------------------
// prep: zero agg, build bf16 hi/lo transposed weight images, detect idx dtype
// ---------------------------------------------------------------------------
__global__ void prep_kernel(const int* __restrict__ ei32,
                            const float* __restrict__ W1,
                            const float* __restrict__ W2) {
    int tid = blockIdx.x * blockDim.x + threadIdx.x;
    int stride = gridDim.x * blockDim.x;
    float* aggf = (float*)g_agg;
    for (int i = tid; i < N_NODES * 4; i += stride) aggf[i] = 0.0f;
    for (int i = tid; i < 128 * 128; i += stride) {
        int n = i >> 7, k = i & 127;
        float v = W1[k * 128 + n] + W1[(128 + k) * 128 + n];   // Wsum^T
        __nv_bfloat16 h = __float2bfloat16_rn(v);
        g_B1hi[n * LDK + k] = h;
        g_B1lo[n * LDK + k] = __float2bfloat16_rn(v - __bfloat162float(h));
        float w = W2[k * 128 + n];                              // W2^T
        __nv_bfloat16 h2 = __float2bfloat16_rn(w);
        g_B2hi[n * LDK + k] = h2;
        g_B2lo[n * LDK + k] = __float2bfloat16_rn(w - __bfloat162float(h2));
    }
    // zero pad columns
    for (int i = tid; i < 128 * (LDK - 128); i += stride) {
        int n = i / (LDK - 128), k = 128 + i % (LDK - 128);
        g_B1hi[n * LDK + k] = __float2bfloat16_rn(0.f);
        g_B1lo[n * LDK + k] = __float2bfloat16_rn(0.f);
        g_B2hi[n * LDK + k] = __float2bfloat16_rn(0.f);
        g_B2lo[n * LDK + k] = __float2bfloat16_rn(0.f);
    }
    if (tid == 0) {
        g_nzero = 0;
        g_idx64 = ((ei32[1] | ei32[3] | ei32[5] | ei32[7]) == 0) ? 1 : 0;
    }
}

// ---------------------------------------------------------------------------
// scatter: one red.global.add.v4.f32 per edge ({ea0,ea1,ea2,1.0})
// ---------------------------------------------------------------------------
__global__ void scatter_kernel(const int* __restrict__ ei32, const float* __restrict__ ea) {
    int e = blockIdx.x * blockDim.x + threadIdx.x;
    if (e >= N_EDGES) return;
    int src;
    if (g_idx64) src = ei32[2 * (N_EDGES + e)];
    else         src = ei32[N_EDGES + e];
    float a0 = ea[e * 3 + 0];
    float a1 = ea[e * 3 + 1];
    float a2 = ea[e * 3 + 2];
    asm volatile("red.global.add.v4.f32 [%0], {%1, %2, %3, %4};"
                 :: "l"(&g_agg[src]), "f"(a0), "f"(a1), "f"(a2), "f"(1.0f)
                 : "memory");
}

// ---------------------------------------------------------------------------
// fused (persistent): B1+B2 resident in SMEM; loop over 128-node tiles
// ---------------------------------------------------------------------------
__global__ __launch_bounds__(THREADS, 1)
void fused_kernel(const float* __restrict__ x,
                  const float* __restrict__ W1,
                  const float* __restrict__ b1g,
                  const float* __restrict__ b2g,
                  float* __restrict__ out) {
    extern __shared__ char smem[];
    __nv_bfloat16* sB1hi = (__nv_bfloat16*)(smem + OFF_B1HI);
    __nv_bfloat16* sB1lo = (__nv_bfloat16*)(smem + OFF_B1LO);
    __nv_bfloat16* sB2hi = (__nv_bfloat16*)(smem + OFF_B2HI);
    __nv_bfloat16* sB2lo = (__nv_bfloat16*)(smem + OFF_B2LO);
    __nv_bfloat16* sAhi  = (__nv_bfloat16*)(smem + OFF_AHI);
    __nv_bfloat16* sAlo  = (__nv_bfloat16*)(smem + OFF_ALO);
    float* sMea = (float*)(smem + OFF_MEA);
    float* sW1c = (float*)(smem + OFF_W1C);
    float* sB1  = (float*)(smem + OFF_B1);
    float* sB2  = (float*)(smem + OFF_B2);

    const int tid = threadIdx.x, wid = tid >> 5, lane = tid & 31;
    const int gID = lane >> 2, tIG = lane & 3;
    const int wr = (wid & 1) * 64;      // warp row base
    const int wc = (wid >> 1) * 32;     // warp col base

    // ---- one-time: biases, W1c, all 4 weight images ----
    if (tid < 128) { sB1[tid] = b1g[tid]; sB2[tid] = b2g[tid]; }
    for (int i = tid; i < 3 * 128; i += THREADS) sW1c[i] = W1[256 * 128 + i];
    {
        const uint4* s1 = (const uint4*)g_B1hi;
        const uint4* s2 = (const uint4*)g_B1lo;
        const uint4* s3 = (const uint4*)g_B2hi;
        const uint4* s4 = (const uint4*)g_B2lo;
        uint4* d1 = (uint4*)sB1hi;
        uint4* d2 = (uint4*)sB1lo;
        uint4* d3 = (uint4*)sB2hi;
        uint4* d4 = (uint4*)sB2lo;
        for (int i = tid; i < 128 * LDK * 2 / 16; i += THREADS) {
            d1[i] = s1[i]; d2[i] = s2[i]; d3[i] = s3[i]; d4[i] = s4[i];
        }
    }
    __syncthreads();

#define MMA_LAYER(SBH, SBL)                                                     \
    _Pragma("unroll")                                                           \
    for (int ks = 0; ks < 8; ks++) {                                            \
        const int k0 = ks * 16 + tIG * 2;                                       \
        uint32_t aH[4][4], aL[4][4], bH[4][2], bL[4][2];                        \
        _Pragma("unroll")                                                       \
        for (int ma = 0; ma < 4; ma++) {                                        \
            int r = wr + ma * 16 + gID;                                         \
            aH[ma][0] = *(const uint32_t*)(sAhi + r * LDK + k0);                \
            aH[ma][1] = *(const uint32_t*)(sAhi + (r + 8) * LDK + k0);          \
            aH[ma][2] = *(const uint32_t*)(sAhi + r * LDK + k0 + 8);            \
            aH[ma][3] = *(const uint32_t*)(sAhi + (r + 8) * LDK + k0 + 8);      \
            aL[ma][0] = *(const uint32_t*)(sAlo + r * LDK + k0);                \
            aL[ma][1] = *(const uint32_t*)(sAlo + (r + 8) * LDK + k0);          \
            aL[ma][2] = *(const uint32_t*)(sAlo + r * LDK + k0 + 8);            \
            aL[ma][3] = *(const uint32_t*)(sAlo + (r + 8) * LDK + k0 + 8);      \
        }                                                                       \
        _Pragma("unroll")                                                       \
        for (int na = 0; na < 4; na++) {                                        \
            int n = wc + na * 8 + gID;                                          \
            bH[na][0] = *(const uint32_t*)((SBH) + n * LDK + k0);               \
            bH[na][1] = *(const uint32_t*)((SBH) + n * LDK + k0 + 8);           \
            bL[na][0] = *(const uint32_t*)((SBL) + n * LDK + k0);               \
            bL[na][1] = *(const uint32_t*)((SBL) + n * LDK + k0 + 8);           \
        }                                                                       \
        _Pragma("unroll")                                                       \
        for (int ma = 0; ma < 4; ma++)                                          \
            _Pragma("unroll")                                                   \
            for (int na = 0; na < 4; na++) {                                    \
                mma_bf16(acc[ma][na], aH[ma], bH[na]);                          \
                mma_bf16(acc[ma][na], aL[ma], bH[na]);                          \
                mma_bf16(acc[ma][na], aH[ma], bL[na]);                          \
            }                                                                   \
    }

    for (int t = blockIdx.x; t < NBLK; t += gridDim.x) {
        const int node0 = t * TM;

        // ---- mea + zero-degree detect ----
        if (tid < TM) {
            int g = node0 + tid;
            float4 a = make_float4(0.f, 0.f, 0.f, 1.f);
            if (g < N_NODES) {
                a = g_agg[g];
                if (a.w == 0.f) {
                    int p = atomicAdd(&g_nzero, 1);
                    if (p >= 0 && p < 4096) g_zlist[p] = g;
                }
            }
            float inv = 1.0f / fmaxf(a.w, 1.0f);
            sMea[tid * 4 + 0] = a.x * inv;
            sMea[tid * 4 + 1] = a.y * inv;
            sMea[tid * 4 + 2] = a.z * inv;
        }

        // ---- x -> sA hi/lo ----
        const float4* x4 = (const float4*)x;
        for (int idx = tid; idx < TM * 32; idx += THREADS) {
            int r = idx >> 5, kq = idx & 31, g = node0 + r;
            float4 v = make_float4(0.f, 0.f, 0.f, 0.f);
            if (g < N_NODES) v = x4[g * 32 + kq];
            int o = r * LDK + kq * 4;
            *(uint32_t*)(sAhi + o)     = pack_bf(v.x, v.y);
            *(uint32_t*)(sAhi + o + 2) = pack_bf(v.z, v.w);
            *(uint32_t*)(sAlo + o)     = pack_bf(bf_resid(v.x), bf_resid(v.y));
            *(uint32_t*)(sAlo + o + 2) = pack_bf(bf_resid(v.z), bf_resid(v.w));
        }
        __syncthreads();

        float acc[4][4][4];
#pragma unroll
        for (int ma = 0; ma < 4; ma++)
#pragma unroll
            for (int na = 0; na < 4; na++)
#pragma unroll
                for (int c = 0; c < 4; c++) acc[ma][na][c] = 0.f;

        MMA_LAYER(sB1hi, sB1lo)
        __syncthreads();   // all reads of sA done before epilogue1 overwrites it

        // ---- epilogue1: h = relu(acc + b1 + mea@W1c) -> sA hi/lo; reset acc ----
#pragma unroll
        for (int ma = 0; ma < 4; ma++) {
            int r0 = wr + ma * 16 + gID;
            float m00 = sMea[r0 * 4], m01 = sMea[r0 * 4 + 1], m02 = sMea[r0 * 4 + 2];
            int r1 = r0 + 8;
            float m10 = sMea[r1 * 4], m11 = sMea[r1 * 4 + 1], m12 = sMea[r1 * 4 + 2];
#pragma unroll
            for (int na = 0; na < 4; na++) {
                int c0 = wc + na * 8 + tIG * 2;
                float e0 = sB1[c0]     + m00 * sW1c[c0]     + m01 * sW1c[128 + c0]     + m02 * sW1c[256 + c0];
                float e1 = sB1[c0 + 1] + m00 * sW1c[c0 + 1] + m01 * sW1c[128 + c0 + 1] + m02 * sW1c[256 + c0 + 1];
                float f0 = sB1[c0]     + m10 * sW1c[c0]     + m11 * sW1c[128 + c0]     + m12 * sW1c[256 + c0];
                float f1 = sB1[c0 + 1] + m10 * sW1c[c0 + 1] + m11 * sW1c[128 + c0 + 1] + m12 * sW1c[256 + c0 + 1];
                float v0 = fmaxf(acc[ma][na][0] + e0, 0.f);
                float v1 = fmaxf(acc[ma][na][1] + e1, 0.f);
                float v2 = fmaxf(acc[ma][na][2] + f0, 0.f);
                float v3 = fmaxf(acc[ma][na][3] + f1, 0.f);
                *(uint32_t*)(sAhi + r0 * LDK + c0) = pack_bf(v0, v1);
                *(uint32_t*)(sAlo + r0 * LDK + c0) = pack_bf(bf_resid(v0), bf_resid(v1));
                *(uint32_t*)(sAhi + r1 * LDK + c0) = pack_bf(v2, v3);
                *(uint32_t*)(sAlo + r1 * LDK + c0) = pack_bf(bf_resid(v2), bf_resid(v3));
#pragma unroll
                for (int c = 0; c < 4; c++) acc[ma][na][c] = 0.f;
            }
        }
        __syncthreads();

        MMA_LAYER(sB2hi, sB2lo)

        // ---- epilogue2: out = acc + b2 (direct global stores, 8B each) ----
#pragma unroll
        for (int ma = 0; ma < 4; ma++) {
            int r0 = wr + ma * 16 + gID;
            int g0 = node0 + r0, g1 = g0 + 8;
#pragma unroll
            for (int na = 0; na < 4; na++) {
                int c0 = wc + na * 8 + tIG * 2;
                if (g0 < N_NODES) {
                    float2 v = make_float2(acc[ma][na][0] + sB2[c0], acc[ma][na][1] + sB2[c0 + 1]);
                    *(float2*)(out + (size_t)g0 * 128 + c0) = v;
                }
                if (g1 < N_NODES) {
                    float2 v = make_float2(acc[ma][na][2] + sB2[c0], acc[ma][na][3] + sB2[c0 + 1]);
                    *(float2*)(out + (size_t)g1 * 128 + c0) = v;
                }
            }
        }
        __syncthreads();   // protect sA from next iteration's writes
    }
#undef MMA_LAYER
}

// ---------------------------------------------------------------------------
// fixup: exact fp32 recompute for zero-degree nodes (expected count: 0)
// ---------------------------------------------------------------------------
__global__ void fixup_kernel(const float* __restrict__ x,
                             const float* __restrict__ W1,
                             const float* __restrict__ b1,
                             const float* __restrict__ W2,
                             const float* __restrict__ b2,
                             float* __restrict__ out) {
    __shared__ float sh[128];
    int nz = *(volatile int*)&g_nzero;
    if (nz > 4096) nz = 4096;
    if (nz <= 0) return;
    int j = threadIdx.x;
    for (int zi = 0; zi < nz; zi++) {
        int n = g_zlist[zi];
        float acc = b1[j];
        for (int k = 0; k < 128; k++) acc = fmaf(x[n * 128 + k], W1[k * 128 + j], acc);
        sh[j] = fmaxf(acc, 0.f);
        __syncthreads();
        float acc2 = b2[j];
        for (int k = 0; k < 128; k++) acc2 = fmaf(sh[k], W2[k * 128 + j], acc2);
        out[n * 128 + j] = acc2;
        __syncthreads();
    }
}

// ---------------------------------------------------------------------------
extern "C" void kernel_launch(void* const* d_in, const int* in_sizes, int n_in,
                              void* d_out, int out_size) {
    const float* x    = (const float*)d_in[0];
    const int*   ei32 = (const int*)d_in[1];
    const float* ea   = (const float*)d_in[2];
    const float* W1   = (const float*)d_in[5];
    const float* b1   = (const float*)d_in[6];
    const float* W2   = (const float*)d_in[7];
    const float* b2   = (const float*)d_in[8];
    float* out = (float*)d_out;

    cudaFuncSetAttribute(fused_kernel, cudaFuncAttributeMaxDynamicSharedMemorySize, SMEM_TOTAL);

    prep_kernel<<<128, 256>>>(ei32, W1, W2);
    scatter_kernel<<<(N_EDGES + 255) / 256, 256>>>(ei32, ea);
    fused_kernel<<<NPERS, THREADS, SMEM_TOTAL>>>(x, W1, b1, b2, out);
    fixup_kernel<<<1, 128>>>(x, W1, b1, W2, b2, out);
}

// round 9
// speedup vs baseline: 3.0463x; 1.0673x over previous
#include <cuda_runtime.h>
#include <cuda_bf16.h>
#include <cstdint>

#define N_NODES 100000
#define N_EDGES 1600000
#define TM 128
#define NBLK ((N_NODES + TM - 1) / TM)
#define THREADS 512
#define NPERS 148     // persistent CTAs (~1 per SM)
#define LDK 136       // padded K stride (odd 16B stride -> conflict-free frag loads)

// ---- SMEM byte offsets (persistent layout: A + B1 + B2 resident together) ----
#define OFF_B1HI 0            // 34816 each  [128][136] bf16
#define OFF_B1LO 34816
#define OFF_B2HI 69632
#define OFF_B2LO 104448
#define OFF_AHI  139264
#define OFF_ALO  174080
#define OFF_MEA  208896       // [128][4] fp32 (col 3 = fixup scratch)
#define OFF_W1C  210944       // [3][128] fp32
#define OFF_B1   212480       // [128] fp32
#define OFF_B2   212992       // [128] fp32
#define OFF_ZB   213504       // [4] uint32 zero-degree ballots
#define SMEM_TOTAL 213536

// ---- global scratch ----
__device__ float4 g_agg[N_NODES];                      // sum_ea0..2, count
__device__ __align__(16) __nv_bfloat16 g_B1hi[128 * LDK];  // [n][k] = Wsum[k][n]
__device__ __align__(16) __nv_bfloat16 g_B1lo[128 * LDK];
__device__ __align__(16) __nv_bfloat16 g_B2hi[128 * LDK];  // [n][k] = W2[k][n]
__device__ __align__(16) __nv_bfloat16 g_B2lo[128 * LDK];
__device__ int g_idx64;

__device__ __forceinline__ uint32_t pack_bf(float a, float b) {
    __nv_bfloat162 t = __floats2bfloat162_rn(a, b);
    return *(uint32_t*)&t;
}
__device__ __forceinline__ float bf_resid(float v) {
    return v - __bfloat162float(__float2bfloat16_rn(v));
}
__device__ __forceinline__ void mma_bf16(float* c, const uint32_t* a, const uint32_t* b) {
    asm volatile(
        "mma.sync.aligned.m16n8k16.row.col.f32.bf16.bf16.f32 "
        "{%0,%1,%2,%3}, {%4,%5,%6,%7}, {%8,%9}, {%0,%1,%2,%3};"
        : "+f"(c[0]), "+f"(c[1]), "+f"(c[2]), "+f"(c[3])
        : "r"(a[0]), "r"(a[1]), "r"(a[2]), "r"(a[3]), "r"(b[0]), "r"(b[1]));
}

// ---------------------------------------------------------------------------
// prep: zero agg, build bf16 hi/lo transposed weight images, detect idx dtype
// ---------------------------------------------------------------------------
__global__ void prep_kernel(const int* __restrict__ ei32,
                            const float* __restrict__ W1,
                            const float* __restrict__ W2) {
    int tid = blockIdx.x * blockDim.x + threadIdx.x;
    int stride = gridDim.x * blockDim.x;
    float* aggf = (float*)g_agg;
    for (int i = tid; i < N_NODES * 4; i += stride) aggf[i] = 0.0f;
    for (int i = tid; i < 128 * 128; i += stride) {
        int n = i >> 7, k = i & 127;
        float v = W1[k * 128 + n] + W1[(128 + k) * 128 + n];   // Wsum^T
        __nv_bfloat16 h = __float2bfloat16_rn(v);
        g_B1hi[n * LDK + k] = h;
        g_B1lo[n * LDK + k] = __float2bfloat16_rn(v - __bfloat162float(h));
        float w = W2[k * 128 + n];                              // W2^T
        __nv_bfloat16 h2 = __float2bfloat16_rn(w);
        g_B2hi[n * LDK + k] = h2;
        g_B2lo[n * LDK + k] = __float2bfloat16_rn(w - __bfloat162float(h2));
    }
    // zero pad columns
    for (int i = tid; i < 128 * (LDK - 128); i += stride) {
        int n = i / (LDK - 128), k = 128 + i % (LDK - 128);
        g_B1hi[n * LDK + k] = __float2bfloat16_rn(0.f);
        g_B1lo[n * LDK + k] = __float2bfloat16_rn(0.f);
        g_B2hi[n * LDK + k] = __float2bfloat16_rn(0.f);
        g_B2lo[n * LDK + k] = __float2bfloat16_rn(0.f);
    }
    if (tid == 0) {
        g_idx64 = ((ei32[1] | ei32[3] | ei32[5] | ei32[7]) == 0) ? 1 : 0;
    }
}

// ---------------------------------------------------------------------------
// scatter: one red.global.add.v4.f32 per edge ({ea0,ea1,ea2,1.0})
// ---------------------------------------------------------------------------
__global__ void scatter_kernel(const int* __restrict__ ei32, const float* __restrict__ ea) {
    int e = blockIdx.x * blockDim.x + threadIdx.x;
    if (e >= N_EDGES) return;
    int src;
    if (g_idx64) src = ei32[2 * (N_EDGES + e)];
    else         src = ei32[N_EDGES + e];
    float a0 = ea[e * 3 + 0];
    float a1 = ea[e * 3 + 1];
    float a2 = ea[e * 3 + 2];
    asm volatile("red.global.add.v4.f32 [%0], {%1, %2, %3, %4};"
                 :: "l"(&g_agg[src]), "f"(a0), "f"(a1), "f"(a2), "f"(1.0f)
                 : "memory");
}

// ---------------------------------------------------------------------------
// fused (persistent, 512 thr, 32x32 warp tiles): B1+B2 resident; inline fixup
// ---------------------------------------------------------------------------
__global__ __launch_bounds__(THREADS, 1)
void fused_kernel(const float* __restrict__ x,
                  const float* __restrict__ W1,
                  const float* __restrict__ b1g,
                  const float* __restrict__ W2,
                  const float* __restrict__ b2g,
                  float* __restrict__ out) {
    extern __shared__ char smem[];
    __nv_bfloat16* sB1hi = (__nv_bfloat16*)(smem + OFF_B1HI);
    __nv_bfloat16* sB1lo = (__nv_bfloat16*)(smem + OFF_B1LO);
    __nv_bfloat16* sB2hi = (__nv_bfloat16*)(smem + OFF_B2HI);
    __nv_bfloat16* sB2lo = (__nv_bfloat16*)(smem + OFF_B2LO);
    __nv_bfloat16* sAhi  = (__nv_bfloat16*)(smem + OFF_AHI);
    __nv_bfloat16* sAlo  = (__nv_bfloat16*)(smem + OFF_ALO);
    float* sMea = (float*)(smem + OFF_MEA);
    float* sW1c = (float*)(smem + OFF_W1C);
    float* sB1  = (float*)(smem + OFF_B1);
    float* sB2  = (float*)(smem + OFF_B2);
    unsigned* sZb = (unsigned*)(smem + OFF_ZB);

    const int tid = threadIdx.x, wid = tid >> 5, lane = tid & 31;
    const int gID = lane >> 2, tIG = lane & 3;
    const int wr = (wid & 3) * 32;      // warp row base (4 groups x 32 rows)
    const int wc = (wid >> 2) * 32;     // warp col base (4 groups x 32 cols)

    // ---- one-time: biases, W1c, all 4 weight images ----
    if (tid < 128) { sB1[tid] = b1g[tid]; sB2[tid] = b2g[tid]; }
    for (int i = tid; i < 3 * 128; i += THREADS) sW1c[i] = W1[256 * 128 + i];
    {
        const uint4* s1 = (const uint4*)g_B1hi;
        const uint4* s2 = (const uint4*)g_B1lo;
        const uint4* s3 = (const uint4*)g_B2hi;
        const uint4* s4 = (const uint4*)g_B2lo;
        uint4* d1 = (uint4*)sB1hi;
        uint4* d2 = (uint4*)sB1lo;
        uint4* d3 = (uint4*)sB2hi;
        uint4* d4 = (uint4*)sB2lo;
        for (int i = tid; i < 128 * LDK * 2 / 16; i += THREADS) {
            d1[i] = s1[i]; d2[i] = s2[i]; d3[i] = s3[i]; d4[i] = s4[i];
        }
    }

#define MMA_LAYER(SBH, SBL)                                                     \
    _Pragma("unroll")                                                           \
    for (int ks = 0; ks < 8; ks++) {                                            \
        const int k0 = ks * 16 + tIG * 2;                                       \
        uint32_t aH[2][4], aL[2][4], bH[4][2], bL[4][2];                        \
        _Pragma("unroll")                                                       \
        for (int ma = 0; ma < 2; ma++) {                                        \
            int r = wr + ma * 16 + gID;                                         \
            aH[ma][0] = *(const uint32_t*)(sAhi + r * LDK + k0);                \
            aH[ma][1] = *(const uint32_t*)(sAhi + (r + 8) * LDK + k0);          \
            aH[ma][2] = *(const uint32_t*)(sAhi + r * LDK + k0 + 8);            \
            aH[ma][3] = *(const uint32_t*)(sAhi + (r + 8) * LDK + k0 + 8);      \
            aL[ma][0] = *(const uint32_t*)(sAlo + r * LDK + k0);                \
            aL[ma][1] = *(const uint32_t*)(sAlo + (r + 8) * LDK + k0);          \
            aL[ma][2] = *(const uint32_t*)(sAlo + r * LDK + k0 + 8);            \
            aL[ma][3] = *(const uint32_t*)(sAlo + (r + 8) * LDK + k0 + 8);      \
        }                                                                       \
        _Pragma("unroll")                                                       \
        for (int na = 0; na < 4; na++) {                                        \
            int n = wc + na * 8 + gID;                                          \
            bH[na][0] = *(const uint32_t*)((SBH) + n * LDK + k0);               \
            bH[na][1] = *(const uint32_t*)((SBH) + n * LDK + k0 + 8);           \
            bL[na][0] = *(const uint32_t*)((SBL) + n * LDK + k0);               \
            bL[na][1] = *(const uint32_t*)((SBL) + n * LDK + k0 + 8);           \
        }                                                                       \
        _Pragma("unroll")                                                       \
        for (int ma = 0; ma < 2; ma++)                                          \
            _Pragma("unroll")                                                   \
            for (int na = 0; na < 4; na++) {                                    \
                mma_bf16(acc[ma][na], aH[ma], bH[na]);                          \
                mma_bf16(acc[ma][na], aL[ma], bH[na]);                          \
                mma_bf16(acc[ma][na], aH[ma], bL[na]);                          \
            }                                                                   \
    }

    for (int t = blockIdx.x; t < NBLK; t += gridDim.x) {
        const int node0 = t * TM;
        __syncthreads();   // one-time loads visible; sZb/sMea safe to overwrite

        // ---- mea + zero-degree ballot (warps 0-3 cover the 128 nodes) ----
        if (tid < TM) {
            int g = node0 + tid;
            float4 a = make_float4(0.f, 0.f, 0.f, 1.f);
            if (g < N_NODES) a = g_agg[g];
            unsigned zb = __ballot_sync(0xffffffffu, (g < N_NODES) && (a.w == 0.f));
            if (lane == 0) sZb[wid] = zb;
            float inv = 1.0f / fmaxf(a.w, 1.0f);
            sMea[tid * 4 + 0] = a.x * inv;
            sMea[tid * 4 + 1] = a.y * inv;
            sMea[tid * 4 + 2] = a.z * inv;
        }

        // ---- x -> sA hi/lo ----
        const float4* x4 = (const float4*)x;
        for (int idx = tid; idx < TM * 32; idx += THREADS) {
            int r = idx >> 5, kq = idx & 31, g = node0 + r;
            float4 v = make_float4(0.f, 0.f, 0.f, 0.f);
            if (g < N_NODES) v = x4[g * 32 + kq];
            int o = r * LDK + kq * 4;
            *(uint32_t*)(sAhi + o)     = pack_bf(v.x, v.y);
            *(uint32_t*)(sAhi + o + 2) = pack_bf(v.z, v.w);
            *(uint32_t*)(sAlo + o)     = pack_bf(bf_resid(v.x), bf_resid(v.y));
            *(uint32_t*)(sAlo + o + 2) = pack_bf(bf_resid(v.z), bf_resid(v.w));
        }
        __syncthreads();

        float acc[2][4][4];
#pragma unroll
        for (int ma = 0; ma < 2; ma++)
#pragma unroll
            for (int na = 0; na < 4; na++)
#pragma unroll
                for (int c = 0; c < 4; c++) acc[ma][na][c] = 0.f;

        MMA_LAYER(sB1hi, sB1lo)
        __syncthreads();   // all reads of sA done before epilogue1 overwrites it

        // ---- epilogue1: h = relu(acc + b1 + mea@W1c) -> sA hi/lo; reset acc ----
#pragma unroll
        for (int ma = 0; ma < 2; ma++) {
            int r0 = wr + ma * 16 + gID;
            float m00 = sMea[r0 * 4], m01 = sMea[r0 * 4 + 1], m02 = sMea[r0 * 4 + 2];
            int r1 = r0 + 8;
            float m10 = sMea[r1 * 4], m11 = sMea[r1 * 4 + 1], m12 = sMea[r1 * 4 + 2];
#pragma unroll
            for (int na = 0; na < 4; na++) {
                int c0 = wc + na * 8 + tIG * 2;
                float e0 = sB1[c0]     + m00 * sW1c[c0]     + m01 * sW1c[128 + c0]     + m02 * sW1c[256 + c0];
                float e1 = sB1[c0 + 1] + m00 * sW1c[c0 + 1] + m01 * sW1c[128 + c0 + 1] + m02 * sW1c[256 + c0 + 1];
                float f0 = sB1[c0]     + m10 * sW1c[c0]     + m11 * sW1c[128 + c0]     + m12 * sW1c[256 + c0];
                float f1 = sB1[c0 + 1] + m10 * sW1c[c0 + 1] + m11 * sW1c[128 + c0 + 1] + m12 * sW1c[256 + c0 + 1];
                float v0 = fmaxf(acc[ma][na][0] + e0, 0.f);
                float v1 = fmaxf(acc[ma][na][1] + e1, 0.f);
                float v2 = fmaxf(acc[ma][na][2] + f0, 0.f);
                float v3 = fmaxf(acc[ma][na][3] + f1, 0.f);
                *(uint32_t*)(sAhi + r0 * LDK + c0) = pack_bf(v0, v1);
                *(uint32_t*)(sAlo + r0 * LDK + c0) = pack_bf(bf_resid(v0), bf_resid(v1));
                *(uint32_t*)(sAhi + r1 * LDK + c0) = pack_bf(v2, v3);
                *(uint32_t*)(sAlo + r1 * LDK + c0) = pack_bf(bf_resid(v2), bf_resid(v3));
#pragma unroll
                for (int c = 0; c < 4; c++) acc[ma][na][c] = 0.f;
            }
        }
        __syncthreads();

        MMA_LAYER(sB2hi, sB2lo)

        // ---- epilogue2: out = acc + b2 (direct global stores, 8B each) ----
#pragma unroll
        for (int ma = 0; ma < 2; ma++) {
            int r0 = wr + ma * 16 + gID;
            int g0 = node0 + r0, g1 = g0 + 8;
#pragma unroll
            for (int na = 0; na < 4; na++) {
                int c0 = wc + na * 8 + tIG * 2;
                if (g0 < N_NODES) {
                    float2 v = make_float2(acc[ma][na][0] + sB2[c0], acc[ma][na][1] + sB2[c0 + 1]);
                    *(float2*)(out + (size_t)g0 * 128 + c0) = v;
                }
                if (g1 < N_NODES) {
                    float2 v = make_float2(acc[ma][na][2] + sB2[c0], acc[ma][na][3] + sB2[c0 + 1]);
                    *(float2*)(out + (size_t)g1 * 128 + c0) = v;
                }
            }
        }
        __syncthreads();   // orders epi2 stores + sA reads before fixup / next iter

        // ---- inline fixup: exact fp32 recompute for zero-degree nodes ----
        {
            unsigned z0 = sZb[0], z1 = sZb[1], z2 = sZb[2], z3 = sZb[3];
            if (z0 | z1 | z2 | z3) {
#pragma unroll 1
                for (int ws = 0; ws < 4; ws++) {
                    unsigned m = sZb[ws];
                    while (m) {
                        int b = __ffs(m) - 1;
                        m &= m - 1;
                        int n = node0 + ws * 32 + b;
                        if (tid < 128) {
                            float a1 = sB1[tid];
                            for (int k = 0; k < 128; k++)
                                a1 = fmaf(x[(size_t)n * 128 + k], W1[k * 128 + tid], a1);
                            sMea[tid * 4 + 3] = fmaxf(a1, 0.f);
                        }
                        __syncthreads();
                        if (tid < 128) {
                            float a2 = sB2[tid];
                            for (int k = 0; k < 128; k++)
                                a2 = fmaf(sMea[k * 4 + 3], W2[k * 128 + tid], a2);
                            out[(size_t)n * 128 + tid] = a2;
                        }
                        __syncthreads();
                    }
                }
            }
        }
    }
#undef MMA_LAYER
}

// ---------------------------------------------------------------------------
extern "C" void kernel_launch(void* const* d_in, const int* in_sizes, int n_in,
                              void* d_out, int out_size) {
    const float* x    = (const float*)d_in[0];
    const int*   ei32 = (const int*)d_in[1];
    const float* ea   = (const float*)d_in[2];
    const float* W1   = (const float*)d_in[5];
    const float* b1   = (const float*)d_in[6];
    const float* W2   = (const float*)d_in[7];
    const float* b2   = (const float*)d_in[8];
    float* out = (float*)d_out;

    cudaFuncSetAttribute(fused_kernel, cudaFuncAttributeMaxDynamicSharedMemorySize, SMEM_TOTAL);

    prep_kernel<<<128, 256>>>(ei32, W1, W2);
    scatter_kernel<<<(N_EDGES + 255) / 256, 256>>>(ei32, ea);
    fused_kernel<<<NPERS, THREADS, SMEM_TOTAL>>>(x, W1, b1, W2, b2, out);
}